// round 16
// baseline (speedup 1.0000x reference)
#include <cuda_runtime.h>
#include <cstdint>

// SJLT: out[b,p] = (1/sqrt(c)) * sum_{d,j: idx[d,j]==p} sign[d,j] * x[b,d]
//
// R9: counting-sorted events -> register accumulation, zero-SMEM scatter.
//  transpose : xT[d][b] (128 B per d).
//  hist      : per-CTA (4096 d) smem histogram of p + per-event rank; writes
//              packed (p|sign) u16, rank u16, per-CTA counts.
//  scan      : per-slice (32768 d = 8 CTAs) bucket exclusive scan -> absolute
//              bucket starts g_bstart[slice][p]; per-CTA bases for fill.
//  fill      : position = ctaBase[p] + rank -> g_events (d<<8 | sign<<7).
//              Deterministic, atomic-free.
//  scatter   : warp = (slice, 32-bucket range). Per bucket: accumulate run in
//              4 register partials (1 uniform ev LDG + 1 xT LDG + FADD per
//              event), flush ONE coalesced STG to g_partial. No SMEM, no
//              atomics, no shuffles.
//  reduce    : sum 31 slice-partials, scale, transpose-write out.

#define CDIM     8
#define PDIM     4096
#define SLICE_D  32768
#define K2D      4096          // d's per hist/fill CTA
#define MAXD     1000000
#define MAXSLICE 31            // ceil(1e6/32768)
#define MAXCTA2  245           // ceil(1e6/4096)

// static scratch (allocation-free rule)
__device__ float    g_xT[(size_t)32 * MAXD];                   // 128 MB
__device__ unsigned g_events[(size_t)CDIM * MAXD];             //  32 MB
__device__ uint4    g_packed[MAXD];                            //  16 MB
__device__ uint4    g_rank[MAXD];                              //  16 MB
__device__ unsigned g_cnt[(size_t)MAXCTA2 * PDIM];             //   4 MB
__device__ unsigned g_ctaBase[(size_t)MAXCTA2 * PDIM];         //   4 MB
__device__ unsigned g_bstart[(size_t)MAXSLICE * PDIM];         // 0.5 MB
__device__ float    g_partial[(size_t)MAXSLICE * PDIM * 32];   //16.3 MB

// ---- transpose: x[b][d] -> xT[d][b] ----
__global__ __launch_bounds__(256)
void sjlt_transpose(const float* __restrict__ x, int D)
{
    __shared__ float tile[64 * 33];
    const int d0   = blockIdx.x * 64;
    const int wid  = threadIdx.x >> 5;
    const int lane = threadIdx.x & 31;
    for (int b = wid; b < 32; b += 8) {
        const float* src = x + (size_t)b * D + d0;
        tile[lane * 33 + b]        = src[lane];
        tile[(lane + 32) * 33 + b] = src[lane + 32];
    }
    __syncthreads();
    for (int dd = wid; dd < 64; dd += 8)
        g_xT[(size_t)(d0 + dd) * 32 + lane] = tile[dd * 33 + lane];
}

// ---- hist: per-CTA histogram + per-event rank ----
__global__ __launch_bounds__(256)
void sjlt_hist(const int4* __restrict__ idx4,
               const int4* __restrict__ sgn4, int D)
{
    __shared__ unsigned s_hist[PDIM];
    const int tid = threadIdx.x;
    for (int i = tid; i < PDIM; i += 256) s_hist[i] = 0;
    __syncthreads();

    const int dBase = blockIdx.x * K2D;
    for (int k = 0; k < K2D / 256; ++k) {
        const int d = dBase + k * 256 + tid;
        if (d < D) {
            const int4 ia = idx4[2 * d], ib = idx4[2 * d + 1];
            const int4 sa = sgn4[2 * d], sb = sgn4[2 * d + 1];
            const int pj[8] = {ia.x, ia.y, ia.z, ia.w, ib.x, ib.y, ib.z, ib.w};
            const int sj[8] = {sa.x, sa.y, sa.z, sa.w, sb.x, sb.y, sb.z, sb.w};
            unsigned pk[8], rk[8];
            #pragma unroll
            for (int j = 0; j < 8; ++j) {
                const int p = pj[j];
                rk[j] = atomicAdd(&s_hist[p], 1u);                 // local rank
                pk[j] = (unsigned)p | ((sj[j] < 0) ? 0x8000u : 0u);
            }
            g_packed[d] = make_uint4(pk[0] | (pk[1] << 16), pk[2] | (pk[3] << 16),
                                     pk[4] | (pk[5] << 16), pk[6] | (pk[7] << 16));
            g_rank[d]   = make_uint4(rk[0] | (rk[1] << 16), rk[2] | (rk[3] << 16),
                                     rk[4] | (rk[5] << 16), rk[6] | (rk[7] << 16));
        }
    }
    __syncthreads();
    unsigned* dst = g_cnt + (size_t)blockIdx.x * PDIM;
    for (int i = tid; i < PDIM; i += 256) dst[i] = s_hist[i];
}

// ---- scan: per-slice exclusive bucket scan + per-CTA bases ----
__global__ __launch_bounds__(512)
void sjlt_scan(int nCta2)
{
    __shared__ unsigned s_sum[PDIM];
    __shared__ unsigned s_w[16];
    const int s    = blockIdx.x;
    const int tid  = threadIdx.x;
    const int lane = tid & 31, wid = tid >> 5;
    const int c0 = s * 8, c1 = min(c0 + 8, nCta2);

    for (int p = tid; p < PDIM; p += 512) {
        unsigned t = 0;
        for (int c = c0; c < c1; ++c) t += g_cnt[(size_t)c * PDIM + p];
        s_sum[p] = t;
    }
    __syncthreads();

    const int base = tid * 8;
    unsigned loc[8], tsum = 0;
    #pragma unroll
    for (int q = 0; q < 8; ++q) { loc[q] = s_sum[base + q]; tsum += loc[q]; }

    unsigned v = tsum;
    #pragma unroll
    for (int o = 1; o < 32; o <<= 1) {
        const unsigned t = __shfl_up_sync(0xffffffffu, v, o);
        if (lane >= o) v += t;
    }
    const unsigned excl = v - tsum;
    if (lane == 31) s_w[wid] = v;
    __syncthreads();
    if (tid == 0) {
        unsigned r = 0;
        for (int w = 0; w < 16; ++w) { const unsigned t = s_w[w]; s_w[w] = r; r += t; }
    }
    __syncthreads();

    unsigned run = (unsigned)(CDIM * SLICE_D) * s + s_w[wid] + excl;  // absolute
    for (int q = 0; q < 8; ++q) {
        const int p = base + q;
        g_bstart[(size_t)s * PDIM + p] = run;
        unsigned r2 = run;
        for (int c = c0; c < c1; ++c) {
            g_ctaBase[(size_t)c * PDIM + p] = r2;
            r2 += g_cnt[(size_t)c * PDIM + p];
        }
        run += loc[q];
    }
}

// ---- fill: scatter events to sorted positions (no atomics) ----
__global__ __launch_bounds__(256)
void sjlt_fill(int D)
{
    __shared__ unsigned s_base[PDIM];
    const int tid = threadIdx.x;
    const unsigned* cb = g_ctaBase + (size_t)blockIdx.x * PDIM;
    for (int i = tid; i < PDIM; i += 256) s_base[i] = cb[i];
    __syncthreads();

    const int dBase = blockIdx.x * K2D;
    for (int k = 0; k < K2D / 256; ++k) {
        const int d = dBase + k * 256 + tid;
        if (d >= D) continue;
        const uint4 pk = g_packed[d], rk = g_rank[d];
        const unsigned db = ((unsigned)d) << 8;
        const unsigned pw[4] = {pk.x, pk.y, pk.z, pk.w};
        const unsigned rw[4] = {rk.x, rk.y, rk.z, rk.w};
        #pragma unroll
        for (int h = 0; h < 4; ++h) {
            const unsigned p0 = pw[h] & 0xFFFFu, p1 = pw[h] >> 16;
            const unsigned r0 = rw[h] & 0xFFFFu, r1 = rw[h] >> 16;
            g_events[s_base[p0 & 0xFFFu] + r0] = db | ((p0 >> 15) << 7);
            g_events[s_base[p1 & 0xFFFu] + r1] = db | ((p1 >> 15) << 7);
        }
    }
}

// ---- scatter: register-accumulated bucket runs, zero SMEM ----
__global__ __launch_bounds__(512, 2)
void sjlt_scatter(int D)
{
    const int wid  = threadIdx.x >> 5;
    const int lane = threadIdx.x & 31;
    const int slice = blockIdx.x >> 3;                 // 8 CTAs per slice
    const int p0    = ((blockIdx.x & 7) * 16 + wid) * 32;   // 32 buckets/warp

    const unsigned* bs = g_bstart + (size_t)slice * PDIM + p0;
    const unsigned endAll =
        min((unsigned)(CDIM * SLICE_D) * (slice + 1), (unsigned)CDIM * (unsigned)D);
    const char* xb = (const char*)g_xT + (lane << 2);

    unsigned start = __ldg(bs);
    for (int r = 0; r < 32; ++r) {
        const unsigned end = (p0 + r + 1 < PDIM) ? __ldg(bs + r + 1) : endAll;
        float a0 = 0.f, a1 = 0.f, a2 = 0.f, a3 = 0.f;
        unsigned i = start;
        for (; i + 4 <= end; i += 4) {
            const unsigned u0 = __ldg(g_events + i);
            const unsigned u1 = __ldg(g_events + i + 1);
            const unsigned u2 = __ldg(g_events + i + 2);
            const unsigned u3 = __ldg(g_events + i + 3);
            const float x0 = __ldg((const float*)(xb + ((u0 >> 1) & 0xFFFFFF80u)));
            const float x1 = __ldg((const float*)(xb + ((u1 >> 1) & 0xFFFFFF80u)));
            const float x2 = __ldg((const float*)(xb + ((u2 >> 1) & 0xFFFFFF80u)));
            const float x3 = __ldg((const float*)(xb + ((u3 >> 1) & 0xFFFFFF80u)));
            a0 += __uint_as_float(__float_as_uint(x0) ^ ((u0 & 0x80u) << 24));
            a1 += __uint_as_float(__float_as_uint(x1) ^ ((u1 & 0x80u) << 24));
            a2 += __uint_as_float(__float_as_uint(x2) ^ ((u2 & 0x80u) << 24));
            a3 += __uint_as_float(__float_as_uint(x3) ^ ((u3 & 0x80u) << 24));
        }
        for (; i < end; ++i) {
            const unsigned u = __ldg(g_events + i);
            const float xv = __ldg((const float*)(xb + ((u >> 1) & 0xFFFFFF80u)));
            a0 += __uint_as_float(__float_as_uint(xv) ^ ((u & 0x80u) << 24));
        }
        g_partial[((size_t)slice * PDIM + p0 + r) * 32 + lane] =
            (a0 + a1) + (a2 + a3);
        start = end;
    }
}

// ---- reduce: sum slices, scale, transpose-write ----
__global__ __launch_bounds__(1024)
void sjlt_reduce(float* __restrict__ out, float scale, int nslice)
{
    __shared__ float s_r[32 * 33];
    const int tid = threadIdx.x;
    const int p0  = blockIdx.x * 32;
    const int pp = tid >> 5, b = tid & 31;
    const float* src = g_partial + ((size_t)(p0 + pp)) * 32 + b;
    float s = 0.0f;
    for (int c = 0; c < nslice; ++c)
        s += src[(size_t)c * (PDIM * 32)];
    s_r[pp * 33 + b] = s * scale;
    __syncthreads();
    const int b2 = tid >> 5, p2 = tid & 31;
    out[(size_t)b2 * PDIM + p0 + p2] = s_r[p2 * 33 + b2];
}

extern "C" void kernel_launch(void* const* d_in, const int* in_sizes, int n_in,
                              void* d_out, int out_size)
{
    const float* x    = (const float*)d_in[0];
    const int4*  idx4 = (const int4*) d_in[1];
    const int4*  sgn4 = (const int4*) d_in[2];

    const int D      = in_sizes[1] / CDIM;                    // 1,000,000
    const int nslice = (D + SLICE_D - 1) / SLICE_D;           // 31
    const int nCta2  = (D + K2D - 1) / K2D;                   // 245
    const float scale = 0.35355339059327373f;                 // 1/sqrt(8)

    sjlt_transpose<<<D / 64, 256>>>(x, D);
    sjlt_hist<<<nCta2, 256>>>(idx4, sgn4, D);
    sjlt_scan<<<nslice, 512>>>(nCta2);
    sjlt_fill<<<nCta2, 256>>>(D);
    sjlt_scatter<<<nslice * 8, 512>>>(D);
    sjlt_reduce<<<PDIM / 32, 1024>>>((float*)d_out, scale, nslice);
}

// round 17
// speedup vs baseline: 1.7179x; 1.7179x over previous
#include <cuda_runtime.h>
#include <cstdint>

// SJLT: out[b,p] = (1/sqrt(c)) * sum_{d,j: idx[d,j]==p} sign[d,j] * x[b,d]
//
// R10 = R8 (event-list, warp-exclusive bin planes, LDS/STS RMW) with the
// occupancy fix: 8 warps / 68.6 KB per CTA -> 3 CTAs/SM (24 warps vs 16).
//   event u32 = d<<8 | sign<<7 | row(7b), row = p&63 (row 64 = pad sink)
//   xT byte offset = (u>>1) & ~127 ; acc row = u & 0x7F  -> no predication.
//   grid = 56 slices x 8 bin-groups; warp w owns bin group*8+w exclusively.

#define PDIM     4096
#define CDIM     8
#define NBIN     64
#define MAXBIN   131072
#define NSLICE   56
#define SWPB     8             // scatter warps per CTA (one bin each)
#define ACCROWS  65
#define ACCSTR   33
#define ACCSZ    (ACCROWS * ACCSTR)        // 2145 floats/warp
#define PCAP     384
#define PACKD    2048
#define PADEV    64u
#define FULLMASK 0xffffffffu

// static scratch (allocation-free rule)
__device__ float    g_xT[(size_t)32 * 1000000];                  // 128 MB
__device__ unsigned g_events[(size_t)NBIN * MAXBIN];             //  32 MB
__device__ float    g_partial[(size_t)NSLICE * PDIM * 32];       //29.4 MB
__device__ int      g_cursor[NBIN];

__global__ void sjlt_zero()
{
    if (threadIdx.x < NBIN) g_cursor[threadIdx.x] = 0;
}

// ---- transpose: x[b][d] -> xT[d][b] ----
__global__ __launch_bounds__(256)
void sjlt_transpose(const float* __restrict__ x, int D)
{
    __shared__ float tile[64 * 33];
    const int d0   = blockIdx.x * 64;
    const int wid  = threadIdx.x >> 5;
    const int lane = threadIdx.x & 31;

    for (int b = wid; b < 32; b += 8) {
        const float* src = x + (size_t)b * D + d0;
        tile[lane * 33 + b]        = src[lane];
        tile[(lane + 32) * 33 + b] = src[lane + 32];
    }
    __syncthreads();
    for (int dd = wid; dd < 64; dd += 8)
        g_xT[(size_t)(d0 + dd) * 32 + lane] = tile[dd * 33 + lane];
}

// ---- pack: bin events by p>>6 ----
extern __shared__ unsigned p_smem[];   // s_buf[NBIN*PCAP] | s_cnt[NBIN]

__global__ __launch_bounds__(256)
void sjlt_pack(const int4* __restrict__ idx4,
               const int4* __restrict__ sgn4, int D)
{
    unsigned* s_buf = p_smem;
    int*      s_cnt = (int*)(p_smem + NBIN * PCAP);
    const int tid  = threadIdx.x;
    const int wid  = tid >> 5;
    const int lane = tid & 31;

    if (tid < NBIN) s_cnt[tid] = 0;
    __syncthreads();

    const int dBase = blockIdx.x * PACKD;
    for (int r = 0; r < PACKD / 256; ++r) {
        const int d = dBase + r * 256 + tid;
        if (d >= D) break;
        const int4 ia = idx4[2 * d], ib = idx4[2 * d + 1];
        const int4 sa = sgn4[2 * d], sb = sgn4[2 * d + 1];
        const int  pj[CDIM] = {ia.x, ia.y, ia.z, ia.w, ib.x, ib.y, ib.z, ib.w};
        const int  sj[CDIM] = {sa.x, sa.y, sa.z, sa.w, sb.x, sb.y, sb.z, sb.w};
        #pragma unroll
        for (int j = 0; j < CDIM; ++j) {
            const unsigned p = (unsigned)pj[j];
            const unsigned u = ((unsigned)d << 8)
                             | ((sj[j] < 0) ? 0x80u : 0u)
                             | (p & 63u);
            const int bin  = (int)(p >> 6);
            const int slot = atomicAdd(&s_cnt[bin], 1);
            if (slot < PCAP) {
                s_buf[bin * PCAP + slot] = u;
            } else {                                  // rare overflow
                const int gs = atomicAdd(&g_cursor[bin], 1);
                g_events[(size_t)bin * MAXBIN + gs] = u;
            }
        }
    }
    __syncthreads();

    for (int bin = wid; bin < NBIN; bin += 8) {
        const int cnt = min(s_cnt[bin], PCAP);
        int base = 0;
        if (lane == 0) base = atomicAdd(&g_cursor[bin], cnt);
        base = __shfl_sync(FULLMASK, base, 0);
        unsigned* dst = g_events + (size_t)bin * MAXBIN + base;
        const unsigned* src = s_buf + bin * PCAP;
        for (int i = lane; i < cnt; i += 32) dst[i] = src[i];
    }
}

// ---- scatter helpers ----
__device__ __forceinline__ void grp_load(unsigned evw, int g, const char* xbase,
                                         unsigned* u, unsigned* xv)
{
    #pragma unroll
    for (int q = 0; q < 8; ++q) {
        u[q]  = __shfl_sync(FULLMASK, evw, g * 8 + q);
        xv[q] = __float_as_uint(
            __ldg((const float*)(xbase + ((u[q] >> 1) & 0xFFFFFF80u))));
    }
}

__device__ __forceinline__ void grp_rmw(float* accl, const unsigned* u,
                                        const unsigned* xv)
{
    #pragma unroll
    for (int q = 0; q < 8; ++q) {
        const unsigned flip = (u[q] & 0x80u) << 24;
        accl[(u[q] & 0x7Fu) * ACCSTR] += __uint_as_float(xv[q] ^ flip);
    }
}

extern __shared__ float s_acc[];   // SWPB * ACCSZ = 68640 B

__global__ __launch_bounds__(SWPB * 32)
void sjlt_scatter()
{
    const int slice = blockIdx.x >> 3;           // 0..55
    const int seg   = blockIdx.x & 7;            // 0..7
    const int wid   = threadIdx.x >> 5;          // 0..7
    const int lane  = threadIdx.x & 31;
    const int bin   = seg * SWPB + wid;          // exclusive owner
    float* acc  = s_acc + wid * ACCSZ;
    float* accl = acc + lane;

    for (int i = lane; i < ACCSZ; i += 32) acc[i] = 0.0f;
    __syncwarp();

    const int cnt = min(g_cursor[bin], MAXBIN);
    const int i0  = (int)((long long)cnt * slice / NSLICE);
    const int i1  = (int)((long long)cnt * (slice + 1) / NSLICE);
    const unsigned* ev = g_events + (size_t)bin * MAXBIN;
    const char* xbase  = (const char*)g_xT + (lane << 2);

    const int nBatch = (i1 - i0 + 31) >> 5;
    unsigned evw = (i0 + lane < i1) ? __ldcs(ev + i0 + lane) : PADEV;

    unsigned uA[8], xA[8], uB[8], xB[8];
    for (int bt = 0; bt < nBatch; ++bt) {
        // prefetch next batch's event words
        unsigned evn = PADEV;
        const int nb = i0 + (bt + 1) * 32 + lane;
        if (nb < i1) evn = __ldcs(ev + nb);

        grp_load(evw, 0, xbase, uA, xA);
        grp_load(evw, 1, xbase, uB, xB);
        grp_rmw(accl, uA, xA);
        grp_load(evw, 2, xbase, uA, xA);
        grp_rmw(accl, uB, xB);
        grp_load(evw, 3, xbase, uB, xB);
        grp_rmw(accl, uA, xA);
        grp_rmw(accl, uB, xB);

        evw = evn;
    }
    __syncwarp();

    // flush rows 0..63 (row 64 = pad sink) -> g_partial[slice][p][b], STG only
    float* dst = g_partial + ((size_t)slice * PDIM + bin * 64) * 32 + lane;
    #pragma unroll 4
    for (int row = 0; row < 64; ++row)
        dst[row * 32] = acc[row * ACCSTR + lane];
}

__global__ __launch_bounds__(1024)
void sjlt_reduce(float* __restrict__ out, float scale)
{
    __shared__ float s_r[32 * 33];
    const int tid = threadIdx.x;
    const int p0  = blockIdx.x * 32;

    const int pp = tid >> 5, b = tid & 31;
    const float* src = g_partial + ((size_t)(p0 + pp)) * 32 + b;
    float s = 0.0f;
    #pragma unroll
    for (int c = 0; c < NSLICE; ++c)
        s += src[(size_t)c * (PDIM * 32)];
    s_r[pp * 33 + b] = s * scale;
    __syncthreads();

    const int b2 = tid >> 5, p2 = tid & 31;
    out[(size_t)b2 * PDIM + p0 + p2] = s_r[p2 * 33 + b2];
}

extern "C" void kernel_launch(void* const* d_in, const int* in_sizes, int n_in,
                              void* d_out, int out_size)
{
    const float* x    = (const float*)d_in[0];
    const int4*  idx4 = (const int4*) d_in[1];
    const int4*  sgn4 = (const int4*) d_in[2];

    const int D       = in_sizes[1] / CDIM;            // 1,000,000
    const float scale = 0.35355339059327373f;          // 1/sqrt(8)

    const int packSm = NBIN * PCAP * 4 + NBIN * 4;             // 98,560 B
    const int scatSm = SWPB * ACCSZ * (int)sizeof(float);      // 68,640 B
    cudaFuncSetAttribute(sjlt_pack,
                         cudaFuncAttributeMaxDynamicSharedMemorySize, packSm);
    cudaFuncSetAttribute(sjlt_scatter,
                         cudaFuncAttributeMaxDynamicSharedMemorySize, scatSm);

    sjlt_zero<<<1, NBIN>>>();
    sjlt_transpose<<<D / 64, 256>>>(x, D);
    sjlt_pack<<<(D + PACKD - 1) / PACKD, 256, packSm>>>(idx4, sgn4, D);
    sjlt_scatter<<<NSLICE * 8, SWPB * 32, scatSm>>>();
    sjlt_reduce<<<PDIM / 32, 1024>>>((float*)d_out, scale);
}